// round 1
// baseline (speedup 1.0000x reference)
#include <cuda_runtime.h>

#define HW    160
#define NIMG  32
#define NBITS 128
#define PADH  166
#define PADW  176   // padded-global row stride (16B aligned)
#define SW    168   // smem tile row stride (floats)
#define TH    16    // output rows per block
#define TROWS (TH + 6)
#define BITG  32    // bits per block

struct __align__(16) BitP {
    int   off1, off2;         // y1*SW + x1 for each interp
    float fx1, fy1, fx2, fy2; // fractional weights
    float c;                  // 0.125 - 0.25*th
    int   pad0;
};

__device__ BitP  g_params[NBITS];
__device__ float g_pad[NIMG * PADH * PADW];

// ---------------------------------------------------------------------------
// Setup: replicate reference index math exactly (f32 arithmetic, trunc-to-zero)
// ---------------------------------------------------------------------------
__global__ void setup_kernel(const float* __restrict__ dx1, const float* __restrict__ dx2,
                             const float* __restrict__ dy1, const float* __restrict__ dy2,
                             const float* __restrict__ th) {
    __shared__ float red[128];
    int t = threadIdx.x;  // 128 threads
    float a = fmaxf(fabsf(dx1[t]), fabsf(dx2[t]));
    float b = fmaxf(fabsf(dy1[t]), fabsf(dy2[t]));
    red[t] = fmaxf(a, b);
    __syncthreads();
    for (int s = 64; s > 0; s >>= 1) {
        if (t < s) red[t] = fmaxf(red[t], red[t + s]);
        __syncthreads();
    }
    float L = red[0];
    int shift = 3 - (int)ceilf(L);   // PAD - p

    BitP bp;
    {
        float dx = dx1[t], dy = dy1[t];
        float fdx = floorf(dx), fdy = floorf(dy);
        int x1 = (int)(L + fdx) + shift;   // trunc toward zero == jnp astype(int32)
        int y1 = (int)(L + fdy) + shift;
        x1 = min(max(x1, 0), 5);           // dynamic_slice start clamp
        y1 = min(max(y1, 0), 5);
        bp.off1 = y1 * SW + x1;
        bp.fx1 = dx - fdx;
        bp.fy1 = dy - fdy;
    }
    {
        float dx = dx2[t], dy = dy2[t];
        float fdx = floorf(dx), fdy = floorf(dy);
        int x1 = (int)(L + fdx) + shift;
        int y1 = (int)(L + fdy) + shift;
        x1 = min(max(x1, 0), 5);
        y1 = min(max(y1, 0), 5);
        bp.off2 = y1 * SW + x1;
        bp.fx2 = dx - fdx;
        bp.fy2 = dy - fdy;
    }
    bp.c = fmaf(-0.25f, th[t], 0.125f);    // (0.5 - th) / 4
    bp.pad0 = 0;
    g_params[t] = bp;
}

// ---------------------------------------------------------------------------
// Pad: channel 1 of x, zero-padded into (NIMG, PADH, PADW)
// ---------------------------------------------------------------------------
__global__ void pad_kernel(const float* __restrict__ x) {
    int idx = blockIdx.x * 256 + threadIdx.x;   // exactly NIMG*PADH*PADW threads
    int n    = idx / (PADH * PADW);
    int rem  = idx - n * (PADH * PADW);
    int r    = rem / PADW;
    int cidx = rem - r * PADW;
    float v = 0.0f;
    int hr = r - 3, wc = cidx - 3;
    if (hr >= 0 && hr < HW && wc >= 0 && wc < HW)
        v = x[((size_t)n * 3 + 1) * (HW * HW) + hr * HW + wc];
    g_pad[idx] = v;
}

// ---------------------------------------------------------------------------
// Main: per block = (n, bit-group of 32, 16-row tile); 160 threads = one row.
// Vertical lerp reuse: each new output row needs only one new horizontal lerp
// per interp (2 LDS + FADD + FFMA).
// ---------------------------------------------------------------------------
__global__ __launch_bounds__(160) void fern_main(float* __restrict__ out) {
    __shared__ float tile[TROWS * SW];
    __shared__ BitP  sp[BITG];

    int w  = threadIdx.x;           // 0..159
    int h0 = blockIdx.x * TH;
    int bg = blockIdx.y;
    int n  = blockIdx.z;

    // Cooperative tile load (vectorized): padded rows h0 .. h0+TROWS-1, cols 0..167
    {
        const float4* src = (const float4*)(g_pad + (size_t)n * PADH * PADW + (size_t)h0 * PADW);
        float4* dst = (float4*)tile;
        const int RW = SW / 4;       // 42 float4 per smem row
        const int SR = PADW / 4;     // 44 float4 per gmem row
        for (int i = w; i < TROWS * RW; i += 160) {
            int r = i / RW, c = i - r * RW;
            dst[r * RW + c] = src[r * SR + c];
        }
    }
    // Params for this bit group -> smem
    {
        const int4* ps = (const int4*)(g_params + bg * BITG);
        int4* pd = (int4*)sp;
        for (int i = w; i < BITG * 2; i += 160) pd[i] = ps[i];
    }
    __syncthreads();

    for (int b = 0; b < BITG; ++b) {
        BitP bp = sp[b];
        const float* q1 = tile + bp.off1 + w;
        const float* q2 = tile + bp.off2 + w;

        float a0 = q1[0], a1 = q1[1];
        float t1 = fmaf(bp.fx1, a1 - a0, a0);
        float b0 = q2[0], b1 = q2[1];
        float t2 = fmaf(bp.fx2, b1 - b0, b0);

        int bit = bg * BITG + b;
        float* op = out + (((size_t)n * NBITS + bit) * HW + h0) * HW + w;

#pragma unroll
        for (int hh = 1; hh <= TH; ++hh) {
            float c0 = q1[hh * SW], c1 = q1[hh * SW + 1];
            float u1 = fmaf(bp.fx1, c1 - c0, c0);
            float d0 = q2[hh * SW], d1 = q2[hh * SW + 1];
            float u2 = fmaf(bp.fx2, d1 - d0, d0);

            float I1 = fmaf(bp.fy1, u1 - t1, t1);
            float I2 = fmaf(bp.fy2, u2 - t2, t2);

            float v = fmaf(0.25f, I1, bp.c);
            v = fmaf(-0.25f, I2, v);
            op[(size_t)(hh - 1) * HW] = __saturatef(v);

            t1 = u1;
            t2 = u2;
        }
    }
}

// ---------------------------------------------------------------------------
extern "C" void kernel_launch(void* const* d_in, const int* in_sizes, int n_in,
                              void* d_out, int out_size) {
    const float* x   = (const float*)d_in[0];
    const float* dx1 = (const float*)d_in[1];
    const float* dx2 = (const float*)d_in[2];
    const float* dy1 = (const float*)d_in[3];
    const float* dy2 = (const float*)d_in[4];
    const float* th  = (const float*)d_in[5];

    setup_kernel<<<1, 128>>>(dx1, dx2, dy1, dy2, th);
    pad_kernel<<<(NIMG * PADH * PADW) / 256, 256>>>(x);

    dim3 grid(HW / TH, NBITS / BITG, NIMG);
    fern_main<<<grid, 160>>>((float*)d_out);
}